// round 1
// baseline (speedup 1.0000x reference)
#include <cuda_runtime.h>
#include <cstdint>

#define N_NODES 50000
#define N_EDGES 800000
#define N_GRAPHS 500

// ---------------- scratch (device globals: allocation-free) ----------------
__device__ __align__(16) float g_feat[N_NODES * 128]; // GEMM output (layer feat)
__device__ __align__(16) float g_agg [N_NODES * 128]; // scatter-agg output
__device__ __align__(16) float g_h   [N_NODES * 128]; // post BN+ReLU activations
__device__ float g_el  [N_NODES * 4];
__device__ float g_er  [N_NODES * 4];
__device__ int   g_nmax[N_NODES * 4];                 // mapped-float segment max
__device__ float g_den [N_NODES * 4];                 // softmax denominator
__device__ float g_e   [N_EDGES * 4];                 // edge scores, then exp()
__device__ float g_bn  [256];                         // [0:128) sum, [128:256) sumsq
__device__ float g_hg  [N_GRAPHS * 32];               // pooled graph features

// monotone float <-> int map for atomicMax on floats (handles negatives)
__device__ __forceinline__ int   fmap (float f) { int i = __float_as_int(f); return i ^ ((i >> 31) & 0x7FFFFFFF); }
__device__ __forceinline__ float funmap(int m)  { int i = m ^ ((m >> 31) & 0x7FFFFFFF); return __int_as_float(i); }

__device__ __forceinline__ void red_add_v4(float* p, float4 v) {
    asm volatile("red.global.add.v4.f32 [%0], {%1,%2,%3,%4};"
                 :: "l"(p), "f"(v.x), "f"(v.y), "f"(v.z), "f"(v.w) : "memory");
}

// ---------------- reset ----------------
__global__ void k_reset(int nagg, int nnh) {
    int i = blockIdx.x * blockDim.x + threadIdx.x;
    if (i < nagg) g_agg[i] = 0.f;
    if (i < nnh) { g_den[i] = 0.f; g_nmax[i] = (int)0x80000000; }
    if (i < 256) g_bn[i] = 0.f;
    if (i < N_GRAPHS * 32) g_hg[i] = 0.f;
}

// ---------------- GEMM (Fout=128, H=4) fused with el/er ----------------
__global__ void k_gemm128(const float* __restrict__ x, const float* __restrict__ W,
                          const float* __restrict__ al, const float* __restrict__ ar) {
    __shared__ float xs[128];
    int row = blockIdx.x, t = threadIdx.x;
    xs[t] = x[row * 128 + t];
    __syncthreads();
    float acc = 0.f;
#pragma unroll 16
    for (int k = 0; k < 128; k++) acc = fmaf(xs[k], __ldg(&W[k * 128 + t]), acc);
    g_feat[row * 128 + t] = acc;
    // head h = t>>5, lane d = t&31; al/ar are [4,32] flattened => index t
    float vl = acc * __ldg(&al[t]);
    float vr = acc * __ldg(&ar[t]);
#pragma unroll
    for (int o = 16; o > 0; o >>= 1) {
        vl += __shfl_down_sync(0xffffffffu, vl, o);
        vr += __shfl_down_sync(0xffffffffu, vr, o);
    }
    if ((t & 31) == 0) { g_el[row * 4 + (t >> 5)] = vl; g_er[row * 4 + (t >> 5)] = vr; }
}

// ---------------- GEMM (Fout=32, H=1), 4 rows per block ----------------
__global__ void k_gemm32(const float* __restrict__ x, const float* __restrict__ W,
                         const float* __restrict__ al, const float* __restrict__ ar) {
    __shared__ float xs[4][128];
    int t = threadIdx.x;
    int r = t >> 5, c = t & 31;
    int row = blockIdx.x * 4 + r;
#pragma unroll
    for (int j = 0; j < 4; j++) xs[r][c + 32 * j] = x[row * 128 + c + 32 * j];
    __syncthreads();
    float acc = 0.f;
#pragma unroll 16
    for (int k = 0; k < 128; k++) acc = fmaf(xs[r][k], __ldg(&W[k * 32 + c]), acc);
    g_feat[row * 32 + c] = acc;
    float vl = acc * __ldg(&al[c]);
    float vr = acc * __ldg(&ar[c]);
#pragma unroll
    for (int o = 16; o > 0; o >>= 1) {
        vl += __shfl_down_sync(0xffffffffu, vl, o);
        vr += __shfl_down_sync(0xffffffffu, vr, o);
    }
    if (c == 0) { g_el[row] = vl; g_er[row] = vr; }
}

// ---------------- edge pass 1: score + leaky relu + segment max ----------------
__global__ void k_escore(const int* __restrict__ src, const int* __restrict__ dst,
                         int shift, int hmask, int EH) {
    int i = blockIdx.x * blockDim.x + threadIdx.x;
    if (i >= EH) return;
    int e = i >> shift, h = i & hmask;
    int H = hmask + 1;
    int s = __ldg(&src[e]), d = __ldg(&dst[e]);
    float v = g_el[s * H + h] + g_er[d * H + h];
    v = v > 0.f ? v : 0.2f * v;
    g_e[i] = v;
    atomicMax(&g_nmax[d * H + h], fmap(v));
}

// ---------------- edge pass 2: exp + segment sum ----------------
__global__ void k_eexp(const int* __restrict__ dst, int shift, int hmask, int EH) {
    int i = blockIdx.x * blockDim.x + threadIdx.x;
    if (i >= EH) return;
    int e = i >> shift, h = i & hmask;
    int H = hmask + 1;
    int d = __ldg(&dst[e]);
    float m = funmap(g_nmax[d * H + h]);
    float ex = __expf(g_e[i] - m);
    g_e[i] = ex;
    atomicAdd(&g_den[d * H + h], ex);
}

// ---------------- edge pass 3: weighted scatter (H=4, D=32) ----------------
// One warp per edge; lane l handles float4 at feature 4l (head = l>>3).
__global__ void k_eagg128(const int* __restrict__ src, const int* __restrict__ dst) {
    int gt = blockIdx.x * blockDim.x + threadIdx.x;
    int w = gt >> 5;
    if (w >= N_EDGES) return;
    int l = threadIdx.x & 31;
    int s = __ldg(&src[w]), d = __ldg(&dst[w]);
    int h = l >> 3;
    float alpha = __ldg(&g_e[w * 4 + h]) / __ldg(&g_den[d * 4 + h]);
    float4 v = *(const float4*)(g_feat + s * 128 + l * 4);
    v.x *= alpha; v.y *= alpha; v.z *= alpha; v.w *= alpha;
    red_add_v4(g_agg + d * 128 + l * 4, v);
}

// ---------------- edge pass 3 for layer 2 (H=1, D=32) ----------------
__global__ void k_eagg32(const int* __restrict__ src, const int* __restrict__ dst) {
    int i = blockIdx.x * blockDim.x + threadIdx.x;
    if (i >= N_EDGES * 8) return;
    int e = i >> 3, g = i & 7;
    int s = __ldg(&src[e]), d = __ldg(&dst[e]);
    float alpha = __ldg(&g_e[e]) / __ldg(&g_den[d]);
    float4 v = *(const float4*)(g_feat + s * 32 + g * 4);
    v.x *= alpha; v.y *= alpha; v.z *= alpha; v.w *= alpha;
    red_add_v4(g_agg + d * 32 + g * 4, v);
}

// ---------------- BN stats: per-feature sum & sumsq over nodes ----------------
__global__ void k_bnstat() {
    __shared__ float sh[256];
    int t = threadIdx.x;
    if (t < 256) sh[t] = 0.f;
    __syncthreads();
    int n = N_NODES * 128;
    for (int i = blockIdx.x * blockDim.x + t; i < n; i += gridDim.x * blockDim.x) {
        float v = g_agg[i];
        int c = i & 127;
        atomicAdd(&sh[c], v);
        atomicAdd(&sh[128 + c], v * v);
    }
    __syncthreads();
    if (t < 256) atomicAdd(&g_bn[t], sh[t]);
}

// ---------------- BN normalize + ReLU (bias b cancels under BN) ----------------
__global__ void k_bnrelu(const float* __restrict__ gamma, const float* __restrict__ beta) {
    int i = blockIdx.x * blockDim.x + threadIdx.x;
    if (i >= N_NODES * 128) return;
    int c = i & 127;
    const float invN = 1.f / (float)N_NODES;
    float mean = g_bn[c] * invN;
    float var = g_bn[128 + c] * invN - mean * mean;
    float v = (g_agg[i] - mean) * rsqrtf(var + 1e-5f) * __ldg(&gamma[c]) + __ldg(&beta[c]);
    g_h[i] = fmaxf(v, 0.f);
}

// ---------------- graph sum-pool (adds layer-2 bias) ----------------
__global__ void k_pool(const int* __restrict__ gid, const float* __restrict__ b2) {
    int i = blockIdx.x * blockDim.x + threadIdx.x;
    if (i >= N_NODES * 32) return;
    int n = i >> 5, d = i & 31;
    atomicAdd(&g_hg[__ldg(&gid[n]) * 32 + d], g_agg[i] + __ldg(&b2[d]));
}

// ---------------- classifier: [500,32] @ [32,10] + bc ----------------
__global__ void k_cls(const float* __restrict__ Wc, const float* __restrict__ bc,
                      float* __restrict__ out) {
    int i = blockIdx.x * blockDim.x + threadIdx.x;
    if (i >= N_GRAPHS * 10) return;
    int g = i / 10, c = i - g * 10;
    float a = __ldg(&bc[c]);
#pragma unroll
    for (int k = 0; k < 32; k++) a = fmaf(g_hg[g * 32 + k], __ldg(&Wc[k * 10 + c]), a);
    out[i] = a;
}

static inline int divup(int a, int b) { return (a + b - 1) / b; }

extern "C" void kernel_launch(void* const* d_in, const int* in_sizes, int n_in,
                              void* d_out, int out_size) {
    const float* x    = (const float*)d_in[0];
    const int*   src  = (const int*)d_in[1];
    const int*   dst  = (const int*)d_in[2];
    const int*   gid  = (const int*)d_in[3];
    const float* W0   = (const float*)d_in[4];
    const float* al0  = (const float*)d_in[5];
    const float* ar0  = (const float*)d_in[6];
    const float* W1   = (const float*)d_in[8];
    const float* al1  = (const float*)d_in[9];
    const float* ar1  = (const float*)d_in[10];
    const float* W2   = (const float*)d_in[12];
    const float* al2  = (const float*)d_in[13];
    const float* ar2  = (const float*)d_in[14];
    const float* b2   = (const float*)d_in[15];
    const float* g0   = (const float*)d_in[16];
    const float* be0  = (const float*)d_in[17];
    const float* g1   = (const float*)d_in[18];
    const float* be1  = (const float*)d_in[19];
    const float* Wc   = (const float*)d_in[20];
    const float* bc   = (const float*)d_in[21];
    float* out = (float*)d_out;

    void* hptr = nullptr;
    cudaGetSymbolAddress(&hptr, g_h);
    const float* hbuf = (const float*)hptr;

    const int B = 256;

    // ---- layer 0 (H=4) ----
    k_reset<<<divup(N_NODES * 128, B), B>>>(N_NODES * 128, N_NODES * 4);
    k_gemm128<<<N_NODES, 128>>>(x, W0, al0, ar0);
    k_escore<<<divup(N_EDGES * 4, B), B>>>(src, dst, 2, 3, N_EDGES * 4);
    k_eexp<<<divup(N_EDGES * 4, B), B>>>(dst, 2, 3, N_EDGES * 4);
    k_eagg128<<<divup(N_EDGES * 32, B), B>>>(src, dst);
    k_bnstat<<<2048, 256>>>();
    k_bnrelu<<<divup(N_NODES * 128, B), B>>>(g0, be0);

    // ---- layer 1 (H=4) ----
    k_reset<<<divup(N_NODES * 128, B), B>>>(N_NODES * 128, N_NODES * 4);
    k_gemm128<<<N_NODES, 128>>>(hbuf, W1, al1, ar1);
    k_escore<<<divup(N_EDGES * 4, B), B>>>(src, dst, 2, 3, N_EDGES * 4);
    k_eexp<<<divup(N_EDGES * 4, B), B>>>(dst, 2, 3, N_EDGES * 4);
    k_eagg128<<<divup(N_EDGES * 32, B), B>>>(src, dst);
    k_bnstat<<<2048, 256>>>();
    k_bnrelu<<<divup(N_NODES * 128, B), B>>>(g1, be1);

    // ---- layer 2 (H=1, D=32) ----
    k_reset<<<divup(N_NODES * 128, B), B>>>(N_NODES * 32, N_NODES);
    k_gemm32<<<N_NODES / 4, 128>>>(hbuf, W2, al2, ar2);
    k_escore<<<divup(N_EDGES, B), B>>>(src, dst, 0, 0, N_EDGES);
    k_eexp<<<divup(N_EDGES, B), B>>>(dst, 0, 0, N_EDGES);
    k_eagg32<<<divup(N_EDGES * 8, B), B>>>(src, dst);

    // ---- pool + classify ----
    k_pool<<<divup(N_NODES * 32, B), B>>>(gid, b2);
    k_cls<<<divup(N_GRAPHS * 10, B), B>>>(Wc, bc, out);
}